// round 11
// baseline (speedup 1.0000x reference)
#include <cuda_runtime.h>
#include <cuda_bf16.h>
#include <math.h>
#include <stdint.h>

#define Nn   100000
#define Ee   400000
#define Gg   2048
#define DINc 128
#define RANKc 256
#define EPSc 1e-5f

// ---------------- persistent scratch (__device__ globals; no allocs) ----------------
// NOTE: g_deg / g_esum rely on zero-at-tail: zero-initialized at module load,
// re-zeroed by k_zero_tail at the end of every call (deterministic invariant).
__device__ float g_t  [(size_t)Nn * RANKc];          // tanh(gemm) output (per layer)
__device__ __nv_bfloat16 g_ah[(size_t)Nn * RANKc];   // agg hi (bf16 split)
__device__ __nv_bfloat16 g_al[(size_t)Nn * RANKc];   // agg lo
__device__ __nv_bfloat16 g_wh[(DINc + 2 * RANKc) * RANKc];  // W^T hi, 3 layers packed
__device__ __nv_bfloat16 g_wl[(DINc + 2 * RANKc) * RANKc];  // W^T lo
__device__ float g_sum[RANKc];
__device__ float g_sq [RANKc];
__device__ float g_af [3 * RANKc];                   // BN affine scale  per layer
__device__ float g_bf [3 * RANKc];                   // BN affine offset per layer
__device__ float g_tmax[3 * (size_t)Gg * RANKc];     // per-graph max of t
__device__ float g_tmin[3 * (size_t)Gg * RANKc];     // per-graph min of t
__device__ int   g_deg[Nn];
__device__ int   g_off[Nn + 1];
__device__ int   g_cur[Nn];
__device__ int   g_srcL[Ee];
__device__ float g_wL  [Ee];
__device__ float g_dinv[Nn];
__device__ float g_esum[Nn];                         // sum of edge weights into node
__device__ int   g_gstart[Gg + 1];                   // graph segment starts (batch sorted)

// ---------------- PTX helpers ----------------
__device__ __forceinline__ void ldm_x4(uint32_t& r0, uint32_t& r1, uint32_t& r2, uint32_t& r3,
                                       uint32_t a) {
    asm volatile("ldmatrix.sync.aligned.m8n8.x4.shared.b16 {%0,%1,%2,%3}, [%4];"
                 : "=r"(r0), "=r"(r1), "=r"(r2), "=r"(r3) : "r"(a));
}
__device__ __forceinline__ void ldm_x2(uint32_t& r0, uint32_t& r1, uint32_t a) {
    asm volatile("ldmatrix.sync.aligned.m8n8.x2.shared.b16 {%0,%1}, [%2];"
                 : "=r"(r0), "=r"(r1) : "r"(a));
}
__device__ __forceinline__ void mma16816(float* c,
                                         uint32_t a0, uint32_t a1, uint32_t a2, uint32_t a3,
                                         uint32_t b0, uint32_t b1) {
    asm volatile("mma.sync.aligned.m16n8k16.row.col.f32.bf16.bf16.f32 "
                 "{%0,%1,%2,%3}, {%4,%5,%6,%7}, {%8,%9}, {%0,%1,%2,%3};"
                 : "+f"(c[0]), "+f"(c[1]), "+f"(c[2]), "+f"(c[3])
                 : "r"(a0), "r"(a1), "r"(a2), "r"(a3), "r"(b0), "r"(b1));
}
__device__ __forceinline__ void cpa16(uint32_t dst, const void* src, int srcBytes) {
    asm volatile("cp.async.cg.shared.global [%0], [%1], 16, %2;"
                 :: "r"(dst), "l"(src), "r"(srcBytes) : "memory");
}
#define CPA_COMMIT() asm volatile("cp.async.commit_group;" ::: "memory")

// ---------------- graph preprocessing ----------------
__global__ void k_deg(const int* __restrict__ ei) {
    int e = blockIdx.x * blockDim.x + threadIdx.x;
    if (e < Ee) atomicAdd(&g_deg[ei[Ee + e]], 1);
}
__global__ void k_scan() {   // exclusive scan of deg -> off/cur; also dinv
    __shared__ int ss[1024];
    int tid = threadIdx.x;
    const int C = (Nn + 1023) / 1024;
    int lo = tid * C;
    int hi = lo + C; if (hi > Nn) hi = Nn; if (lo > Nn) lo = Nn;
    int s = 0;
    for (int i = lo; i < hi; i++) s += g_deg[i];
    ss[tid] = s;
    __syncthreads();
    for (int d = 1; d < 1024; d <<= 1) {
        int v = (tid >= d) ? ss[tid - d] : 0;
        __syncthreads();
        ss[tid] += v;
        __syncthreads();
    }
    int base = (tid > 0) ? ss[tid - 1] : 0;
    for (int i = lo; i < hi; i++) {
        g_off[i] = base;
        g_cur[i] = base;
        g_dinv[i] = rsqrtf((float)(g_deg[i] + 1));
        base += g_deg[i];
    }
    if (tid == 1023) g_off[Nn] = ss[1023];
}
__global__ void k_csr(const int* __restrict__ ei) {
    int e = blockIdx.x * blockDim.x + threadIdx.x;
    if (e < Ee) {
        int s = ei[e];
        int d = ei[Ee + e];
        int p = atomicAdd(&g_cur[d], 1);
        float w = g_dinv[s];
        g_srcL[p] = s;
        g_wL[p]   = w;
        atomicAdd(&g_esum[d], w);
    }
}
__global__ void k_gstart(const int* __restrict__ batch) {
    int n = blockIdx.x * blockDim.x + threadIdx.x;
    if (n >= Nn) return;
    int b = batch[n];
    if (n == 0) {
        for (int g = 0; g <= b; g++) g_gstart[g] = 0;
    } else {
        int pb = batch[n - 1];
        for (int g = pb + 1; g <= b; g++) g_gstart[g] = n;
    }
    if (n == Nn - 1) {
        for (int g = b + 1; g <= Gg; g++) g_gstart[g] = Nn;
    }
}
// zero-at-tail: restore g_deg / g_esum invariant for the next call
__global__ void k_zero_tail() {
    int i = blockIdx.x * blockDim.x + threadIdx.x;
    if (i < Nn) { g_deg[i] = 0; g_esum[i] = 0.0f; }
}

// ---------------- W -> transposed bf16 hi/lo, all 3 layers ----------------
__device__ __forceinline__ void wsplit(float x, __nv_bfloat16* h, __nv_bfloat16* l) {
    __nv_bfloat16 hh = __float2bfloat16(x);
    *h = hh;
    *l = __float2bfloat16(x - __bfloat162float(hh));
}
__global__ void k_wconv_all(const float* __restrict__ W0,
                            const float* __restrict__ W1,
                            const float* __restrict__ W2) {
    int idx = blockIdx.x * blockDim.x + threadIdx.x;
    if (idx < 32768) {                       // layer 0: [n][k], K=128
        int n = idx >> 7, k = idx & 127;
        wsplit(W0[(size_t)k * RANKc + n], &g_wh[idx], &g_wl[idx]);
    } else if (idx < 98304) {                // layer 1: K=256
        int j = idx - 32768; int n = j >> 8, k = j & 255;
        wsplit(W1[(size_t)k * RANKc + n], &g_wh[idx], &g_wl[idx]);
    } else if (idx < 163840) {               // layer 2: K=256
        int j = idx - 98304; int n = j >> 8, k = j & 255;
        wsplit(W2[(size_t)k * RANKc + n], &g_wh[idx], &g_wl[idx]);
    }
}

// ---------------- aggregation: float4 lanes, multi-node blocks, MLP-4 edge loop -----
template<int K, bool FIRST>
__global__ void __launch_bounds__(256) k_agg_t(const float* __restrict__ hin, int layer) {
    constexpr int LPN = K / 4;            // lanes per node (float4 each)
    constexpr int NPB = 256 / LPN;        // nodes per block
    const int tid  = threadIdx.x;
    const int node = blockIdx.x * NPB + tid / LPN;
    const int lane = tid % LPN;
    if (node >= Nn) return;
    const float* __restrict__ h = FIRST ? hin : (const float*)g_t;
    const float* __restrict__ hp = h + lane * 4;

    float dn = g_dinv[node];
    float4 sf = *(const float4*)&hp[(size_t)node * K];
    float4 acc = make_float4(dn * sf.x, dn * sf.y, dn * sf.z, dn * sf.w);

    int i  = g_off[node];
    int e1 = g_off[node + 1];
    for (; i + 4 <= e1; i += 4) {
        int s0 = g_srcL[i + 0], s1 = g_srcL[i + 1], s2 = g_srcL[i + 2], s3 = g_srcL[i + 3];
        float w0 = g_wL[i + 0], w1 = g_wL[i + 1], w2 = g_wL[i + 2], w3 = g_wL[i + 3];
        float4 v0 = *(const float4*)&hp[(size_t)s0 * K];
        float4 v1 = *(const float4*)&hp[(size_t)s1 * K];
        float4 v2 = *(const float4*)&hp[(size_t)s2 * K];
        float4 v3 = *(const float4*)&hp[(size_t)s3 * K];
        acc.x += w0 * v0.x + w1 * v1.x + w2 * v2.x + w3 * v3.x;
        acc.y += w0 * v0.y + w1 * v1.y + w2 * v2.y + w3 * v3.y;
        acc.z += w0 * v0.z + w1 * v1.z + w2 * v2.z + w3 * v3.z;
        acc.w += w0 * v0.w + w1 * v1.w + w2 * v2.w + w3 * v3.w;
    }
    if (i + 2 <= e1) {
        int s0 = g_srcL[i], s1 = g_srcL[i + 1];
        float w0 = g_wL[i], w1 = g_wL[i + 1];
        float4 v0 = *(const float4*)&hp[(size_t)s0 * K];
        float4 v1 = *(const float4*)&hp[(size_t)s1 * K];
        acc.x += w0 * v0.x + w1 * v1.x;
        acc.y += w0 * v0.y + w1 * v1.y;
        acc.z += w0 * v0.z + w1 * v1.z;
        acc.w += w0 * v0.w + w1 * v1.w;
        i += 2;
    }
    if (i < e1) {
        float w0 = g_wL[i];
        float4 v0 = *(const float4*)&hp[(size_t)g_srcL[i] * K];
        acc.x += w0 * v0.x; acc.y += w0 * v0.y; acc.z += w0 * v0.z; acc.w += w0 * v0.w;
    }

    float4 out;
    if (!FIRST) {
        int fi = (layer - 1) * RANKc + lane * 4;
        float4 a = *(const float4*)&g_af[fi];
        float4 b = *(const float4*)&g_bf[fi];
        float cb = dn * (g_esum[node] + dn);
        out.x = a.x * (dn * acc.x) + b.x * cb;
        out.y = a.y * (dn * acc.y) + b.y * cb;
        out.z = a.z * (dn * acc.z) + b.z * cb;
        out.w = a.w * (dn * acc.w) + b.w * cb;
    } else {
        out = make_float4(dn * acc.x, dn * acc.y, dn * acc.z, dn * acc.w);
    }

    __nv_bfloat16 h0 = __float2bfloat16(out.x), h1 = __float2bfloat16(out.y);
    __nv_bfloat16 h2 = __float2bfloat16(out.z), h3 = __float2bfloat16(out.w);
    __nv_bfloat16 l0 = __float2bfloat16(out.x - __bfloat162float(h0));
    __nv_bfloat16 l1 = __float2bfloat16(out.y - __bfloat162float(h1));
    __nv_bfloat16 l2 = __float2bfloat16(out.z - __bfloat162float(h2));
    __nv_bfloat16 l3 = __float2bfloat16(out.w - __bfloat162float(h3));
    __nv_bfloat162 ph0 = {h0, h1}, ph1 = {h2, h3};
    __nv_bfloat162 pl0 = {l0, l1}, pl1 = {l2, l3};
    size_t o = (size_t)node * K + lane * 4;
    *(uint2*)&g_ah[o] = make_uint2(*(uint32_t*)&ph0, *(uint32_t*)&ph1);
    *(uint2*)&g_al[o] = make_uint2(*(uint32_t*)&pl0, *(uint32_t*)&pl1);
}

// ======================= bf16-split GEMM: 128M x 256N CTA, 3-stage cp.async =========
// 8 warps, warp tile 64x64 (wm 2 x wn 4). A read ONCE per layer. Fused BN col stats.
#define ASW 40
#define A_MAT  (128 * ASW * 2)          // 10240 B
#define W_MAT  (256 * ASW * 2)          // 20480 B
#define STG_B  (2 * A_MAT + 2 * W_MAT)  // 61440 B: [Ah][Al][Wh][Wl]
#define NSTG   3
#define SMEM_MMA (NSTG * STG_B)         // 184320 B

__global__ void __launch_bounds__(256, 1) k_mma(const float* __restrict__ bias,
                                                int K, int wofs) {
    extern __shared__ char dsm[];
    const uint32_t dsb = (uint32_t)__cvta_generic_to_shared(dsm);
    __shared__ float sS[256];
    __shared__ float sQ[256];

    const int tid  = threadIdx.x;
    const int lane = tid & 31;
    const int wid  = tid >> 5;
    const int wm   = wid & 1;        // 2 warp rows (64 M)
    const int wn   = wid >> 1;       // 4 warp cols (64 N)
    const int bm   = blockIdx.x * 128;

    float c[4][8][4];
#pragma unroll
    for (int i = 0; i < 4; i++)
#pragma unroll
        for (int j = 0; j < 8; j++)
#pragma unroll
            for (int e = 0; e < 4; e++) c[i][j][e] = 0.0f;

    const int a_row = wm * 64 + (lane & 15);
    const int a_col = (lane >> 4) * 8;
    const int b_row = wn * 64 + (lane & 7);
    const int b_col = ((lane >> 3) & 1) * 8;

    const int nchunks = K >> 5;
    const int r0 = tid >> 2, u0 = tid & 3;   // A: 2 iters r0+64t; W: 4 iters

    auto load_chunk = [&](int cidx) {
        int k0 = cidx * 32;
        uint32_t sb = dsb + (cidx % NSTG) * STG_B;
        // A tile: 128 rows x 32 cols, hi+lo
#pragma unroll
        for (int t = 0; t < 2; t++) {
            int r = r0 + t * 64;
            int gr = bm + r;
            int pa = (gr < Nn) ? 16 : 0;
            int cgr = (gr < Nn) ? gr : (Nn - 1);
            uint32_t doff = (uint32_t)(r * ASW + u0 * 8) * 2;
            cpa16(sb + 0 * A_MAT + doff, &g_ah[(size_t)cgr * K + k0 + u0 * 8], pa);
            cpa16(sb + 1 * A_MAT + doff, &g_al[(size_t)cgr * K + k0 + u0 * 8], pa);
        }
        // W tile: 256 n-rows x 32 cols, hi+lo
        uint32_t wb = sb + 2 * A_MAT;
#pragma unroll
        for (int t = 0; t < 4; t++) {
            int r = r0 + t * 64;
            uint32_t doff = (uint32_t)(r * ASW + u0 * 8) * 2;
            cpa16(wb + 0 * W_MAT + doff, &g_wh[wofs + (size_t)r * K + k0 + u0 * 8], 16);
            cpa16(wb + 1 * W_MAT + doff, &g_wl[wofs + (size_t)r * K + k0 + u0 * 8], 16);
        }
        CPA_COMMIT();
    };

    load_chunk(0);
    if (nchunks > 1) load_chunk(1);

    for (int cc = 0; cc < nchunks; cc++) {
        if (cc == nchunks - 1) asm volatile("cp.async.wait_group 0;" ::: "memory");
        else                   asm volatile("cp.async.wait_group 1;" ::: "memory");
        __syncthreads();

        uint32_t sb = dsb + (cc % NSTG) * STG_B;
        uint32_t aH = sb, aL = sb + A_MAT;
        uint32_t wH = sb + 2 * A_MAT, wL = wH + W_MAT;
#pragma unroll
        for (int kk = 0; kk < 2; kk++) {
            uint32_t bh[8][2], bl[8][2];
#pragma unroll
            for (int nt = 0; nt < 8; nt++) {
                uint32_t boff = (uint32_t)((b_row + nt * 8) * ASW + b_col + kk * 16) * 2;
                ldm_x2(bh[nt][0], bh[nt][1], wH + boff);
                ldm_x2(bl[nt][0], bl[nt][1], wL + boff);
            }
#pragma unroll
            for (int mt = 0; mt < 4; mt++) {
                uint32_t aoff = (uint32_t)((a_row + mt * 16) * ASW + a_col + kk * 16) * 2;
                uint32_t ah0, ah1, ah2, ah3, al0, al1, al2, al3;
                ldm_x4(ah0, ah1, ah2, ah3, aH + aoff);
                ldm_x4(al0, al1, al2, al3, aL + aoff);
#pragma unroll
                for (int nt = 0; nt < 8; nt++) {
                    mma16816(c[mt][nt], ah0, ah1, ah2, ah3, bh[nt][0], bh[nt][1]);
                    mma16816(c[mt][nt], ah0, ah1, ah2, ah3, bl[nt][0], bl[nt][1]);
                    mma16816(c[mt][nt], al0, al1, al2, al3, bh[nt][0], bh[nt][1]);
                }
            }
        }
        __syncthreads();
        if (cc + 2 < nchunks) load_chunk(cc + 2);
    }

    // ---- epilogue: bias + tanh -> g_t, fused BN column stats ----
    if (tid < 256) { sS[tid] = 0.0f; sQ[tid] = 0.0f; }
    __syncthreads();

    const int rbase = bm + wm * 64 + (lane >> 2);
    const int cbase = wn * 64 + (lane & 3) * 2;
    float cs[16], cq[16];
#pragma unroll
    for (int j = 0; j < 16; j++) { cs[j] = 0.0f; cq[j] = 0.0f; }

#pragma unroll
    for (int nt = 0; nt < 8; nt++) {
        int col = cbase + nt * 8;
        float b0 = bias[col];
        float b1 = bias[col + 1];
#pragma unroll
        for (int mt = 0; mt < 4; mt++) {
#pragma unroll
            for (int hfl = 0; hfl < 2; hfl++) {
                int row = rbase + mt * 16 + hfl * 8;
                float t0 = 0.0f, t1 = 0.0f;
                if (row < Nn) {
                    t0 = tanhf(c[mt][nt][hfl * 2 + 0] + b0);
                    t1 = tanhf(c[mt][nt][hfl * 2 + 1] + b1);
                    *(float2*)&g_t[(size_t)row * RANKc + col] = make_float2(t0, t1);
                }
                cs[nt * 2 + 0] += t0;  cq[nt * 2 + 0] += t0 * t0;
                cs[nt * 2 + 1] += t1;  cq[nt * 2 + 1] += t1 * t1;
            }
        }
    }
    // reduce over the 8 lanes sharing the same column set (lane bits 2..4)
#pragma unroll
    for (int j = 0; j < 16; j++) {
#pragma unroll
        for (int o = 4; o <= 16; o <<= 1) {
            cs[j] += __shfl_xor_sync(0xffffffffu, cs[j], o);
            cq[j] += __shfl_xor_sync(0xffffffffu, cq[j], o);
        }
    }
    if (lane < 4) {
#pragma unroll
        for (int nt = 0; nt < 8; nt++) {
#pragma unroll
            for (int e = 0; e < 2; e++) {
                int lc = wn * 64 + lane * 2 + nt * 8 + e;
                atomicAdd(&sS[lc], cs[nt * 2 + e]);
                atomicAdd(&sQ[lc], cq[nt * 2 + e]);
            }
        }
    }
    __syncthreads();
    if (tid < 256) {
        atomicAdd(&g_sum[tid], sS[tid]);
        atomicAdd(&g_sq [tid], sQ[tid]);
    }
}

// ---------------- BN stats -> affine (a, b); re-zero accumulators ----------------
__global__ void k_meanvar(const float* __restrict__ gamma,
                          const float* __restrict__ beta, int layer) {
    int f = threadIdx.x;
    float mu  = g_sum[f] / (float)Nn;
    float var = g_sq[f] / (float)Nn - mu * mu;
    if (var < 0.0f) var = 0.0f;
    float rs = rsqrtf(var + EPSc);
    float a = gamma[f] * rs;
    g_af[layer * RANKc + f] = a;
    g_bf[layer * RANKc + f] = beta[f] - mu * a;
    g_sum[f] = 0.0f;
    g_sq[f]  = 0.0f;
}

// ---------------- per-graph max/min of t: 64 lanes x float4, 4 graphs/block --------
__global__ void __launch_bounds__(256) k_pool(int layer) {
    int g    = blockIdx.x * 4 + threadIdx.x / 64;
    int lane = threadIdx.x % 64;
    if (g >= Gg) return;
    int lo = g_gstart[g], hi = g_gstart[g + 1];
    float ninf = __int_as_float(0xff800000), pinf = __int_as_float(0x7f800000);
    float4 mx = make_float4(ninf, ninf, ninf, ninf);
    float4 mn = make_float4(pinf, pinf, pinf, pinf);
    const float* __restrict__ tp = (const float*)g_t + lane * 4;
    for (int r = lo; r < hi; r++) {
        float4 v = *(const float4*)&tp[(size_t)r * RANKc];
        mx.x = fmaxf(mx.x, v.x); mx.y = fmaxf(mx.y, v.y);
        mx.z = fmaxf(mx.z, v.z); mx.w = fmaxf(mx.w, v.w);
        mn.x = fminf(mn.x, v.x); mn.y = fminf(mn.y, v.y);
        mn.z = fminf(mn.z, v.z); mn.w = fminf(mn.w, v.w);
    }
    size_t o = ((size_t)layer * Gg + g) * RANKc + lane * 4;
    *(float4*)&g_tmax[o] = mx;
    *(float4*)&g_tmin[o] = mn;
}

// ---------------- decode: pooled y = a>0 ? a*max(t)+b : a*min(t)+b ----------------
__global__ void k_decode(float* __restrict__ out) {
    int i = blockIdx.x * blockDim.x + threadIdx.x;
    if (i < 3 * Gg * RANKc) {
        int l = i / (Gg * RANKc);
        int g = (i / RANKc) % Gg;
        int f = i % RANKc;
        float r = 0.0f;
        if (g_gstart[g] < g_gstart[g + 1]) {
            float a = g_af[l * RANKc + f];
            float b = g_bf[l * RANKc + f];
            float v = 0.0f;
            if (a > 0.0f)      v = a * g_tmax[i];
            else if (a < 0.0f) v = a * g_tmin[i];
            r = v + b;
        }
        out[i] = r;
    }
}

// ---------------- launch ----------------
extern "C" void kernel_launch(void* const* d_in, const int* in_sizes, int n_in,
                              void* d_out, int out_size) {
    const float* x     = (const float*)d_in[0];
    const int*   ei    = (const int*)d_in[1];
    const int*   batch = (const int*)d_in[2];
    const float* W[3]  = {(const float*)d_in[3],  (const float*)d_in[7],  (const float*)d_in[11]};
    const float* b[3]  = {(const float*)d_in[4],  (const float*)d_in[8],  (const float*)d_in[12]};
    const float* ga[3] = {(const float*)d_in[5],  (const float*)d_in[9],  (const float*)d_in[13]};
    const float* be[3] = {(const float*)d_in[6],  (const float*)d_in[10], (const float*)d_in[14]};
    float* out = (float*)d_out;

    cudaFuncSetAttribute(k_mma, cudaFuncAttributeMaxDynamicSharedMemorySize, SMEM_MMA);

    // g_deg / g_esum are zero on entry (module init or previous call's tail)
    k_deg<<<(Ee + 255) / 256, 256>>>(ei);                 // launch 1
    k_scan<<<1, 1024>>>();                                // launch 2
    k_csr<<<(Ee + 255) / 256, 256>>>(ei);                 // launch 3

    const int wofsL[3] = {0, DINc * RANKc, DINc * RANKc + RANKc * RANKc};
    for (int l = 0; l < 3; l++) {
        if (l == 0) k_agg_t<DINc, true><<<(Nn * (DINc / 4) + 255) / 256, 256>>>(x, 0);   // launch 4 (ncu)
        else        k_agg_t<RANKc, false><<<(Nn * (RANKc / 4) + 255) / 256, 256>>>(nullptr, l);
        if (l == 0) k_wconv_all<<<640, 256>>>(W[0], W[1], W[2]);
        int K = (l == 0) ? DINc : RANKc;
        k_mma<<<(Nn + 127) / 128, 256, SMEM_MMA>>>(b[l], K, wofsL[l]);
        k_meanvar<<<1, 256>>>(ga[l], be[l], l);
        if (l == 0) k_gstart<<<(Nn + 255) / 256, 256>>>(batch);
        k_pool<<<512, 256>>>(l);
    }
    k_decode<<<(3 * Gg * RANKc + 255) / 256, 256>>>(out);
    k_zero_tail<<<(Nn + 255) / 256, 256>>>();
}

// round 13
// speedup vs baseline: 1.1212x; 1.1212x over previous
#include <cuda_runtime.h>
#include <cuda_bf16.h>
#include <math.h>
#include <stdint.h>

#define Nn   100000
#define Ee   400000
#define Gg   2048
#define DINc 128
#define RANKc 256
#define EPSc 1e-5f

// ---------------- persistent scratch (__device__ globals; no allocs) ----------------
// g_deg / g_esum rely on zero-at-tail: zero at module load, re-zeroed each call's end.
__device__ float g_t  [(size_t)Nn * RANKc];
__device__ __nv_bfloat16 g_ah[(size_t)Nn * RANKc];
__device__ __nv_bfloat16 g_al[(size_t)Nn * RANKc];
__device__ __nv_bfloat16 g_wh[(DINc + 2 * RANKc) * RANKc];
__device__ __nv_bfloat16 g_wl[(DINc + 2 * RANKc) * RANKc];
__device__ float g_sum[RANKc];
__device__ float g_sq [RANKc];
__device__ float g_af [3 * RANKc];
__device__ float g_bf [3 * RANKc];
__device__ float g_tmax[3 * (size_t)Gg * RANKc];
__device__ float g_tmin[3 * (size_t)Gg * RANKc];
__device__ int   g_deg[Nn];
__device__ int   g_off[Nn + 1];
__device__ int   g_cur[Nn];
__device__ int   g_srcL[Ee];
__device__ float g_wL  [Ee];
__device__ float g_dinv[Nn];
__device__ float g_esum[Nn];
__device__ int   g_gstart[Gg + 1];

// ---------------- PTX helpers ----------------
__device__ __forceinline__ float tanh_fast(float x) {
    float y;
    asm("tanh.approx.f32 %0, %1;" : "=f"(y) : "f"(x));
    return y;
}
__device__ __forceinline__ void ldm_x4(uint32_t& r0, uint32_t& r1, uint32_t& r2, uint32_t& r3,
                                       uint32_t a) {
    asm volatile("ldmatrix.sync.aligned.m8n8.x4.shared.b16 {%0,%1,%2,%3}, [%4];"
                 : "=r"(r0), "=r"(r1), "=r"(r2), "=r"(r3) : "r"(a));
}
__device__ __forceinline__ void ldm_x2(uint32_t& r0, uint32_t& r1, uint32_t a) {
    asm volatile("ldmatrix.sync.aligned.m8n8.x2.shared.b16 {%0,%1}, [%2];"
                 : "=r"(r0), "=r"(r1) : "r"(a));
}
__device__ __forceinline__ void mma16816(float* c,
                                         uint32_t a0, uint32_t a1, uint32_t a2, uint32_t a3,
                                         uint32_t b0, uint32_t b1) {
    asm volatile("mma.sync.aligned.m16n8k16.row.col.f32.bf16.bf16.f32 "
                 "{%0,%1,%2,%3}, {%4,%5,%6,%7}, {%8,%9}, {%0,%1,%2,%3};"
                 : "+f"(c[0]), "+f"(c[1]), "+f"(c[2]), "+f"(c[3])
                 : "r"(a0), "r"(a1), "r"(a2), "r"(a3), "r"(b0), "r"(b1));
}
__device__ __forceinline__ void cpa16(uint32_t dst, const void* src, int srcBytes) {
    asm volatile("cp.async.cg.shared.global [%0], [%1], 16, %2;"
                 :: "r"(dst), "l"(src), "r"(srcBytes) : "memory");
}
#define CPA_COMMIT() asm volatile("cp.async.commit_group;" ::: "memory")

// ---------------- graph preprocessing ----------------
__global__ void k_deg(const int* __restrict__ ei) {
    int e = blockIdx.x * blockDim.x + threadIdx.x;
    if (e < Ee) atomicAdd(&g_deg[ei[Ee + e]], 1);
}
__global__ void k_scan() {
    __shared__ int ss[1024];
    int tid = threadIdx.x;
    const int C = (Nn + 1023) / 1024;
    int lo = tid * C;
    int hi = lo + C; if (hi > Nn) hi = Nn; if (lo > Nn) lo = Nn;
    int s = 0;
    for (int i = lo; i < hi; i++) s += g_deg[i];
    ss[tid] = s;
    __syncthreads();
    for (int d = 1; d < 1024; d <<= 1) {
        int v = (tid >= d) ? ss[tid - d] : 0;
        __syncthreads();
        ss[tid] += v;
        __syncthreads();
    }
    int base = (tid > 0) ? ss[tid - 1] : 0;
    for (int i = lo; i < hi; i++) {
        g_off[i] = base;
        g_cur[i] = base;
        g_dinv[i] = rsqrtf((float)(g_deg[i] + 1));
        base += g_deg[i];
    }
    if (tid == 1023) g_off[Nn] = ss[1023];
}
__global__ void k_csr(const int* __restrict__ ei) {
    int e = blockIdx.x * blockDim.x + threadIdx.x;
    if (e < Ee) {
        int s = ei[e];
        int d = ei[Ee + e];
        int p = atomicAdd(&g_cur[d], 1);
        float w = g_dinv[s];
        g_srcL[p] = s;
        g_wL[p]   = w;
        atomicAdd(&g_esum[d], w);
    }
}
__global__ void k_gstart(const int* __restrict__ batch) {
    int n = blockIdx.x * blockDim.x + threadIdx.x;
    if (n >= Nn) return;
    int b = batch[n];
    if (n == 0) {
        for (int g = 0; g <= b; g++) g_gstart[g] = 0;
    } else {
        int pb = batch[n - 1];
        for (int g = pb + 1; g <= b; g++) g_gstart[g] = n;
    }
    if (n == Nn - 1) {
        for (int g = b + 1; g <= Gg; g++) g_gstart[g] = Nn;
    }
}
__global__ void k_zero_tail() {
    int i = blockIdx.x * blockDim.x + threadIdx.x;
    if (i < Nn) { g_deg[i] = 0; g_esum[i] = 0.0f; }
}

// ---------------- W -> transposed bf16 hi/lo, all 3 layers ----------------
__device__ __forceinline__ void wsplit(float x, __nv_bfloat16* h, __nv_bfloat16* l) {
    __nv_bfloat16 hh = __float2bfloat16(x);
    *h = hh;
    *l = __float2bfloat16(x - __bfloat162float(hh));
}
__global__ void k_wconv_all(const float* __restrict__ W0,
                            const float* __restrict__ W1,
                            const float* __restrict__ W2) {
    int idx = blockIdx.x * blockDim.x + threadIdx.x;
    if (idx < 32768) {
        int n = idx >> 7, k = idx & 127;
        wsplit(W0[(size_t)k * RANKc + n], &g_wh[idx], &g_wl[idx]);
    } else if (idx < 98304) {
        int j = idx - 32768; int n = j >> 8, k = j & 255;
        wsplit(W1[(size_t)k * RANKc + n], &g_wh[idx], &g_wl[idx]);
    } else if (idx < 163840) {
        int j = idx - 98304; int n = j >> 8, k = j & 255;
        wsplit(W2[(size_t)k * RANKc + n], &g_wh[idx], &g_wl[idx]);
    }
}

// ---------------- aggregation: float4 lanes, multi-node blocks, MLP-4 edge loop -----
template<int K, bool FIRST>
__global__ void __launch_bounds__(256) k_agg_t(const float* __restrict__ hin, int layer) {
    constexpr int LPN = K / 4;
    constexpr int NPB = 256 / LPN;
    const int tid  = threadIdx.x;
    const int node = blockIdx.x * NPB + tid / LPN;
    const int lane = tid % LPN;
    if (node >= Nn) return;
    const float* __restrict__ h = FIRST ? hin : (const float*)g_t;
    const float* __restrict__ hp = h + lane * 4;

    float dn = g_dinv[node];
    float4 sf = *(const float4*)&hp[(size_t)node * K];
    float4 acc = make_float4(dn * sf.x, dn * sf.y, dn * sf.z, dn * sf.w);

    int i  = g_off[node];
    int e1 = g_off[node + 1];
    for (; i + 4 <= e1; i += 4) {
        int s0 = g_srcL[i + 0], s1 = g_srcL[i + 1], s2 = g_srcL[i + 2], s3 = g_srcL[i + 3];
        float w0 = g_wL[i + 0], w1 = g_wL[i + 1], w2 = g_wL[i + 2], w3 = g_wL[i + 3];
        float4 v0 = *(const float4*)&hp[(size_t)s0 * K];
        float4 v1 = *(const float4*)&hp[(size_t)s1 * K];
        float4 v2 = *(const float4*)&hp[(size_t)s2 * K];
        float4 v3 = *(const float4*)&hp[(size_t)s3 * K];
        acc.x += w0 * v0.x + w1 * v1.x + w2 * v2.x + w3 * v3.x;
        acc.y += w0 * v0.y + w1 * v1.y + w2 * v2.y + w3 * v3.y;
        acc.z += w0 * v0.z + w1 * v1.z + w2 * v2.z + w3 * v3.z;
        acc.w += w0 * v0.w + w1 * v1.w + w2 * v2.w + w3 * v3.w;
    }
    if (i + 2 <= e1) {
        int s0 = g_srcL[i], s1 = g_srcL[i + 1];
        float w0 = g_wL[i], w1 = g_wL[i + 1];
        float4 v0 = *(const float4*)&hp[(size_t)s0 * K];
        float4 v1 = *(const float4*)&hp[(size_t)s1 * K];
        acc.x += w0 * v0.x + w1 * v1.x;
        acc.y += w0 * v0.y + w1 * v1.y;
        acc.z += w0 * v0.z + w1 * v1.z;
        acc.w += w0 * v0.w + w1 * v1.w;
        i += 2;
    }
    if (i < e1) {
        float w0 = g_wL[i];
        float4 v0 = *(const float4*)&hp[(size_t)g_srcL[i] * K];
        acc.x += w0 * v0.x; acc.y += w0 * v0.y; acc.z += w0 * v0.z; acc.w += w0 * v0.w;
    }

    float4 out;
    if (!FIRST) {
        int fi = (layer - 1) * RANKc + lane * 4;
        float4 a = *(const float4*)&g_af[fi];
        float4 b = *(const float4*)&g_bf[fi];
        float cb = dn * (g_esum[node] + dn);
        out.x = a.x * (dn * acc.x) + b.x * cb;
        out.y = a.y * (dn * acc.y) + b.y * cb;
        out.z = a.z * (dn * acc.z) + b.z * cb;
        out.w = a.w * (dn * acc.w) + b.w * cb;
    } else {
        out = make_float4(dn * acc.x, dn * acc.y, dn * acc.z, dn * acc.w);
    }

    __nv_bfloat16 h0 = __float2bfloat16(out.x), h1 = __float2bfloat16(out.y);
    __nv_bfloat16 h2 = __float2bfloat16(out.z), h3 = __float2bfloat16(out.w);
    __nv_bfloat16 l0 = __float2bfloat16(out.x - __bfloat162float(h0));
    __nv_bfloat16 l1 = __float2bfloat16(out.y - __bfloat162float(h1));
    __nv_bfloat16 l2 = __float2bfloat16(out.z - __bfloat162float(h2));
    __nv_bfloat16 l3 = __float2bfloat16(out.w - __bfloat162float(h3));
    __nv_bfloat162 ph0 = {h0, h1}, ph1 = {h2, h3};
    __nv_bfloat162 pl0 = {l0, l1}, pl1 = {l2, l3};
    size_t o = (size_t)node * K + lane * 4;
    *(uint2*)&g_ah[o] = make_uint2(*(uint32_t*)&ph0, *(uint32_t*)&ph1);
    *(uint2*)&g_al[o] = make_uint2(*(uint32_t*)&pl0, *(uint32_t*)&pl1);
}

// ======================= bf16-split GEMM (R9 shape): 128x128 tile, occ 2 ============
#define ASW 40
#define MAT_B  (128 * ASW * 2)
#define STAGE_B (4 * MAT_B)
#define SMEM_MMA (2 * STAGE_B)

__global__ void __launch_bounds__(256, 2) k_mma(const float* __restrict__ bias,
                                                int K, int wofs) {
    extern __shared__ char dsm[];
    const uint32_t dsb = (uint32_t)__cvta_generic_to_shared(dsm);
    __shared__ float sS[128];
    __shared__ float sQ[128];

    const int tid  = threadIdx.x;
    const int lane = tid & 31;
    const int wid  = tid >> 5;
    const int wm   = wid & 1;
    const int wn   = wid >> 1;
    const int bm   = blockIdx.y * 128;
    const int bn   = blockIdx.x * 128;

    float c[4][4][4];
#pragma unroll
    for (int i = 0; i < 4; i++)
#pragma unroll
        for (int j = 0; j < 4; j++)
#pragma unroll
            for (int e = 0; e < 4; e++) c[i][j][e] = 0.0f;

    const int a_row = wm * 64 + (lane & 15);
    const int a_col = (lane >> 4) * 8;
    const int b_row = wn * 32 + (lane & 7);
    const int b_col = ((lane >> 3) & 1) * 8;

    const int nchunks = K >> 5;
    const int r0 = tid >> 2, u0 = tid & 3;

    auto load_chunk = [&](int cidx, int s) {
        int k0 = cidx * 32;
        uint32_t sb = dsb + s * STAGE_B;
#pragma unroll
        for (int t = 0; t < 2; t++) {
            int r = r0 + t * 64;
            int u = u0;
            int gr = bm + r;
            int pa = (gr < Nn) ? 16 : 0;
            int cgr = (gr < Nn) ? gr : (Nn - 1);
            uint32_t doff = (uint32_t)(r * ASW + u * 8) * 2;
            cpa16(sb + 0 * MAT_B + doff, &g_ah[(size_t)cgr * K + k0 + u * 8], pa);
            cpa16(sb + 1 * MAT_B + doff, &g_al[(size_t)cgr * K + k0 + u * 8], pa);
            cpa16(sb + 2 * MAT_B + doff, &g_wh[wofs + (size_t)(bn + r) * K + k0 + u * 8], 16);
            cpa16(sb + 3 * MAT_B + doff, &g_wl[wofs + (size_t)(bn + r) * K + k0 + u * 8], 16);
        }
    };

    load_chunk(0, 0);
    CPA_COMMIT();

    for (int cc = 0; cc < nchunks; cc++) {
        if (cc + 1 < nchunks) {
            load_chunk(cc + 1, (cc + 1) & 1);
            CPA_COMMIT();
            asm volatile("cp.async.wait_group 1;" ::: "memory");
        } else {
            asm volatile("cp.async.wait_group 0;" ::: "memory");
        }
        __syncthreads();

        uint32_t sb = dsb + (cc & 1) * STAGE_B;
        uint32_t aH = sb, aL = sb + MAT_B, bH = sb + 2 * MAT_B, bL = sb + 3 * MAT_B;
#pragma unroll
        for (int kk = 0; kk < 2; kk++) {
            uint32_t bh[4][2], bl[4][2];
#pragma unroll
            for (int nt = 0; nt < 4; nt++) {
                uint32_t boff = (uint32_t)((b_row + nt * 8) * ASW + b_col + kk * 16) * 2;
                ldm_x2(bh[nt][0], bh[nt][1], bH + boff);
                ldm_x2(bl[nt][0], bl[nt][1], bL + boff);
            }
#pragma unroll
            for (int mt = 0; mt < 4; mt++) {
                uint32_t aoff = (uint32_t)((a_row + mt * 16) * ASW + a_col + kk * 16) * 2;
                uint32_t ah0, ah1, ah2, ah3, al0, al1, al2, al3;
                ldm_x4(ah0, ah1, ah2, ah3, aH + aoff);
                ldm_x4(al0, al1, al2, al3, aL + aoff);
#pragma unroll
                for (int nt = 0; nt < 4; nt++) {
                    mma16816(c[mt][nt], ah0, ah1, ah2, ah3, bh[nt][0], bh[nt][1]);
                    mma16816(c[mt][nt], ah0, ah1, ah2, ah3, bl[nt][0], bl[nt][1]);
                    mma16816(c[mt][nt], al0, al1, al2, al3, bh[nt][0], bh[nt][1]);
                }
            }
        }
        __syncthreads();
    }

    // ---- epilogue: bias + tanh.approx -> g_t, fused BN column stats ----
    if (tid < 128) { sS[tid] = 0.0f; sQ[tid] = 0.0f; }
    __syncthreads();

    const int rbase = bm + wm * 64 + (lane >> 2);
    const int cbase = bn + wn * 32 + (lane & 3) * 2;
    float cs[8], cq[8];
#pragma unroll
    for (int j = 0; j < 8; j++) { cs[j] = 0.0f; cq[j] = 0.0f; }

#pragma unroll
    for (int nt = 0; nt < 4; nt++) {
        int col = cbase + nt * 8;
        float b0 = bias[col];
        float b1 = bias[col + 1];
#pragma unroll
        for (int mt = 0; mt < 4; mt++) {
#pragma unroll
            for (int hfl = 0; hfl < 2; hfl++) {
                int row = rbase + mt * 16 + hfl * 8;
                float t0 = 0.0f, t1 = 0.0f;
                if (row < Nn) {
                    t0 = tanh_fast(c[mt][nt][hfl * 2 + 0] + b0);
                    t1 = tanh_fast(c[mt][nt][hfl * 2 + 1] + b1);
                    *(float2*)&g_t[(size_t)row * RANKc + col] = make_float2(t0, t1);
                }
                cs[nt * 2 + 0] += t0;  cq[nt * 2 + 0] += t0 * t0;
                cs[nt * 2 + 1] += t1;  cq[nt * 2 + 1] += t1 * t1;
            }
        }
    }
#pragma unroll
    for (int j = 0; j < 8; j++) {
#pragma unroll
        for (int o = 4; o <= 16; o <<= 1) {
            cs[j] += __shfl_xor_sync(0xffffffffu, cs[j], o);
            cq[j] += __shfl_xor_sync(0xffffffffu, cq[j], o);
        }
    }
    if (lane < 4) {
#pragma unroll
        for (int nt = 0; nt < 4; nt++) {
#pragma unroll
            for (int e = 0; e < 2; e++) {
                int lc = wn * 32 + (lane & 3) * 2 + nt * 8 + e;
                atomicAdd(&sS[lc], cs[nt * 2 + e]);
                atomicAdd(&sQ[lc], cq[nt * 2 + e]);
            }
        }
    }
    __syncthreads();
    if (tid < 128) {
        atomicAdd(&g_sum[bn + tid], sS[tid]);
        atomicAdd(&g_sq [bn + tid], sQ[tid]);
    }
}

// ---------------- BN stats -> affine (a, b); re-zero accumulators ----------------
__global__ void k_meanvar(const float* __restrict__ gamma,
                          const float* __restrict__ beta, int layer) {
    int f = threadIdx.x;
    float mu  = g_sum[f] / (float)Nn;
    float var = g_sq[f] / (float)Nn - mu * mu;
    if (var < 0.0f) var = 0.0f;
    float rs = rsqrtf(var + EPSc);
    float a = gamma[f] * rs;
    g_af[layer * RANKc + f] = a;
    g_bf[layer * RANKc + f] = beta[f] - mu * a;
    g_sum[f] = 0.0f;
    g_sq[f]  = 0.0f;
}

// ---------------- per-graph max/min of t: 64 lanes x float4, 4 graphs/block --------
__global__ void __launch_bounds__(256) k_pool(int layer) {
    int g    = blockIdx.x * 4 + threadIdx.x / 64;
    int lane = threadIdx.x % 64;
    if (g >= Gg) return;
    int lo = g_gstart[g], hi = g_gstart[g + 1];
    float ninf = __int_as_float(0xff800000), pinf = __int_as_float(0x7f800000);
    float4 mx = make_float4(ninf, ninf, ninf, ninf);
    float4 mn = make_float4(pinf, pinf, pinf, pinf);
    const float* __restrict__ tp = (const float*)g_t + lane * 4;
    for (int r = lo; r < hi; r++) {
        float4 v = *(const float4*)&tp[(size_t)r * RANKc];
        mx.x = fmaxf(mx.x, v.x); mx.y = fmaxf(mx.y, v.y);
        mx.z = fmaxf(mx.z, v.z); mx.w = fmaxf(mx.w, v.w);
        mn.x = fminf(mn.x, v.x); mn.y = fminf(mn.y, v.y);
        mn.z = fminf(mn.z, v.z); mn.w = fminf(mn.w, v.w);
    }
    size_t o = ((size_t)layer * Gg + g) * RANKc + lane * 4;
    *(float4*)&g_tmax[o] = mx;
    *(float4*)&g_tmin[o] = mn;
}

// ---------------- decode: pooled y = a>0 ? a*max(t)+b : a*min(t)+b ----------------
__global__ void k_decode(float* __restrict__ out) {
    int i = blockIdx.x * blockDim.x + threadIdx.x;
    if (i < 3 * Gg * RANKc) {
        int l = i / (Gg * RANKc);
        int g = (i / RANKc) % Gg;
        int f = i % RANKc;
        float r = 0.0f;
        if (g_gstart[g] < g_gstart[g + 1]) {
            float a = g_af[l * RANKc + f];
            float b = g_bf[l * RANKc + f];
            float v = 0.0f;
            if (a > 0.0f)      v = a * g_tmax[i];
            else if (a < 0.0f) v = a * g_tmin[i];
            r = v + b;
        }
        out[i] = r;
    }
}

// ---------------- launch ----------------
extern "C" void kernel_launch(void* const* d_in, const int* in_sizes, int n_in,
                              void* d_out, int out_size) {
    const float* x     = (const float*)d_in[0];
    const int*   ei    = (const int*)d_in[1];
    const int*   batch = (const int*)d_in[2];
    const float* W[3]  = {(const float*)d_in[3],  (const float*)d_in[7],  (const float*)d_in[11]};
    const float* b[3]  = {(const float*)d_in[4],  (const float*)d_in[8],  (const float*)d_in[12]};
    const float* ga[3] = {(const float*)d_in[5],  (const float*)d_in[9],  (const float*)d_in[13]};
    const float* be[3] = {(const float*)d_in[6],  (const float*)d_in[10], (const float*)d_in[14]};
    float* out = (float*)d_out;

    cudaFuncSetAttribute(k_mma, cudaFuncAttributeMaxDynamicSharedMemorySize, SMEM_MMA);

    // g_deg / g_esum are zero on entry (module init or previous call's tail)
    k_deg<<<(Ee + 255) / 256, 256>>>(ei);
    k_scan<<<1, 1024>>>();
    k_csr<<<(Ee + 255) / 256, 256>>>(ei);

    const int wofsL[3] = {0, DINc * RANKc, DINc * RANKc + RANKc * RANKc};
    for (int l = 0; l < 3; l++) {
        if (l == 0) k_agg_t<DINc, true><<<(Nn * (DINc / 4) + 255) / 256, 256>>>(x, 0);
        else        k_agg_t<RANKc, false><<<(Nn * (RANKc / 4) + 255) / 256, 256>>>(nullptr, l);
        if (l == 0) k_wconv_all<<<640, 256>>>(W[0], W[1], W[2]);
        int K = (l == 0) ? DINc : RANKc;
        dim3 gg(RANKc / 128, (Nn + 127) / 128);
        k_mma<<<gg, 256, SMEM_MMA>>>(b[l], K, wofsL[l]);
        k_meanvar<<<1, 256>>>(ga[l], be[l], l);
        if (l == 0) k_gstart<<<(Nn + 255) / 256, 256>>>(batch);
        k_pool<<<512, 256>>>(l);
    }
    k_decode<<<(3 * Gg * RANKc + 255) / 256, 256>>>(out);
    k_zero_tail<<<(Nn + 255) / 256, 256>>>();
}